// round 7
// baseline (speedup 1.0000x reference)
#include <cuda_runtime.h>
#include <cuda_bf16.h>
#include <math.h>

#define NB 64
#define NP 16320
#define NC 81
#define NO 50
#define NPB 64              // prior-blocks per batch (64*256 = 16384 >= NP)
#define NRID (NB*NPB)       // 4096 regions
#define NPCW 2048           // posconf warps
#define OGRP 10             // truths per bestprior block
#define FULLMASK 0xffffffffu

// ---------------- static scratch (no allocations) ----------------
__device__ unsigned long long g_best[NB * NO];
__device__ float    g_ce[(size_t)NB * NP];    // mining array (pos -> 0)
__device__ int2     g_pos[(size_t)NB * NP];   // compact positive list {g, conf_t}
__device__ int      g_npt;
__device__ int      g_np_part[NRID];
__device__ double   g_loc_part[NRID];
__device__ double   g_obj_part[NRID];
__device__ int      g_fixnpos[NB];
__device__ double   g_fixloc[NB];
__device__ double   g_fixobj[NB];
__device__ int2     g_fixbuf[NB * 100];       // (g, signed conf_t), ct==0 invalid
__device__ double   g_pcpart[NPCW];
__device__ double   g_minepart[NB];

__device__ __forceinline__ float sl1_row(const float* lp, float4 pr, float4 tb) {
    float gx = ((tb.x + tb.z) * 0.5f - pr.x) / (0.1f * pr.z);
    float gy = ((tb.y + tb.w) * 0.5f - pr.y) / (0.1f * pr.w);
    float gw = logf((tb.z - tb.x) / pr.z) / 0.2f;
    float gh = logf((tb.w - tb.y) / pr.w) / 0.2f;
    float d0 = lp[0] - gx, d1 = lp[1] - gy, d2 = lp[2] - gw, d3 = lp[3] - gh;
    #define SL1(d) ((fabsf(d) < 1.f) ? 0.5f * (d) * (d) : fabsf(d) - 0.5f)
    return SL1(d0) + SL1(d1) + SL1(d2) + SL1(d3);
    #undef SL1
}

// ---------------- init ----------------
__global__ void k_init() {
    int i = blockIdx.x * blockDim.x + threadIdx.x;
    if (i == 0) g_npt = 0;
    if (i < NRID) { g_np_part[i] = 0; g_loc_part[i] = 0.0; g_obj_part[i] = 0.0; }
    if (i < NB) { g_minepart[i] = 0.0; g_fixnpos[i] = 0; g_fixloc[i] = 0.0; g_fixobj[i] = 0.0; }
    if (i < NB * 100) g_fixbuf[i] = make_int2(0, 0);
}

// ---------------- best prior per truth: register-resident, no collectives -----
__global__ void __launch_bounds__(256) k_bestprior(const float4* __restrict__ priors,
                                                   const float* __restrict__ targets) {
    const int b = blockIdx.y, og = blockIdx.x;   // og in [0,5)
    const int t = threadIdx.x, lane = t & 31, w = t >> 5;
    float4 tb[OGRP]; float ta[OGRP];
    #pragma unroll
    for (int j = 0; j < OGRP; j++) {
        const float* tp = targets + ((size_t)b * NO + og * OGRP + j) * 5;
        tb[j] = make_float4(tp[0], tp[1], tp[2], tp[3]);
        ta[j] = (tb[j].z - tb[j].x) * (tb[j].w - tb[j].y);
    }
    unsigned long long best[OGRP];
    #pragma unroll
    for (int j = 0; j < OGRP; j++) best[j] = 0ull;

    for (int p = t; p < NP; p += 256) {
        float4 pr = priors[p];
        float px1 = pr.x - pr.z * 0.5f, py1 = pr.y - pr.w * 0.5f;
        float px2 = pr.x + pr.z * 0.5f, py2 = pr.y + pr.w * 0.5f;
        float areaP = (px2 - px1) * (py2 - py1);
        unsigned invp = ~(unsigned)p;
        #pragma unroll
        for (int j = 0; j < OGRP; j++) {
            float ix = fmaxf(fminf(px2, tb[j].z) - fmaxf(px1, tb[j].x), 0.f);
            float iy = fmaxf(fminf(py2, tb[j].w) - fmaxf(py1, tb[j].y), 0.f);
            float inter = ix * iy;
            float iou = inter / (ta[j] + areaP - inter);
            unsigned long long pk =
                (((unsigned long long)__float_as_uint(iou)) << 32) | invp;
            if (pk > best[j]) best[j] = pk;     // iou max; tie -> lowest p
        }
    }
    __shared__ unsigned long long s_red[OGRP][8];
    #pragma unroll
    for (int j = 0; j < OGRP; j++) {
        unsigned long long v = best[j];
        #pragma unroll
        for (int s = 16; s; s >>= 1) {
            unsigned long long o2 = __shfl_xor_sync(FULLMASK, v, s);
            if (o2 > v) v = o2;
        }
        if (lane == 0) s_red[j][w] = v;
    }
    __syncthreads();
    if (t < OGRP) {
        unsigned long long v = s_red[t][0];
        #pragma unroll
        for (int i = 1; i < 8; i++) if (s_red[t][i] > v) v = s_red[t][i];
        g_best[b * NO + og * OGRP + t] = v;
    }
}

// ---------------- per-prior: best truth + losses (pure ALU/FMA loop) ----------
__global__ void __launch_bounds__(256) k_matchpos(
    const float* __restrict__ loc, const float2* __restrict__ obj,
    const float4* __restrict__ priors, const float* __restrict__ targets)
{
    const int b = blockIdx.y, pb = blockIdx.x, rid = b * NPB + pb;
    const int t = threadIdx.x, lane = t & 31, w = t >> 5;
    __shared__ float4 tbox[NO];
    __shared__ float  tarea[NO], tlabel[NO];
    __shared__ int   s_wc[8];
    __shared__ float s_sl[8], s_so[8];
    __shared__ int   s_base;

    if (t < NO) {
        const float* tp = targets + ((size_t)b * NO + t) * 5;
        float4 bx = make_float4(tp[0], tp[1], tp[2], tp[3]);
        tbox[t] = bx;
        tarea[t] = (bx.z - bx.x) * (bx.w - bx.y);
        tlabel[t] = tp[4];
    }
    __syncthreads();

    const int p = pb * 256 + t;
    const bool valid = p < NP;
    float4 pr;
    float px1, py1, px2, py2, areaP;
    if (valid) {
        pr = priors[p];
        px1 = pr.x - pr.z * 0.5f; py1 = pr.y - pr.w * 0.5f;
        px2 = pr.x + pr.z * 0.5f; py2 = pr.y + pr.w * 0.5f;
        areaP = (px2 - px1) * (py2 - py1);
    } else {
        px1 = py1 = px2 = py2 = 1e30f;  // inter = 0 -> iou = 0
        areaP = 0.f;
    }

    float bestv = -1.f; int besto = 0;
    #pragma unroll 5
    for (int o = 0; o < NO; o++) {
        float4 tbo = tbox[o];
        float ix = fmaxf(fminf(px2, tbo.z) - fmaxf(px1, tbo.x), 0.f);
        float iy = fmaxf(fminf(py2, tbo.w) - fmaxf(py1, tbo.y), 0.f);
        float inter = ix * iy;
        float iou = inter / (tarea[o] + areaP - inter);
        if (iou > bestv) { bestv = iou; besto = o; }  // first max (tie rule)
    }

    bool pos = false; int conf_t = 0; float lossl = 0.f, ceo = 0.f;
    if (valid) {
        conf_t = (bestv < 0.5f) ? 0 : ((int)tlabel[besto] + 1);
        pos = conf_t > 0;
        size_t g = (size_t)b * NP + p;
        float2 ob = obj[g];
        float lseo = fmaxf(ob.x, ob.y) + log1pf(__expf(-fabsf(ob.x - ob.y)));
        g_ce[g] = pos ? 0.f : (lseo - ob.x);            // ce_c(neg) == ce_o(neg)
        if (pos) {
            ceo = lseo - ob.y;
            lossl = sl1_row(loc + g * 4, pr, tbox[besto]);
        }
    }

    unsigned bal = __ballot_sync(FULLMASK, pos);
    int rank = __popc(bal & ((1u << lane) - 1));
    float sl = lossl, so = ceo;
    #pragma unroll
    for (int s = 16; s; s >>= 1) {
        sl += __shfl_xor_sync(FULLMASK, sl, s);
        so += __shfl_xor_sync(FULLMASK, so, s);
    }
    if (lane == 0) { s_wc[w] = __popc(bal); s_sl[w] = sl; s_so[w] = so; }
    __syncthreads();
    if (t == 0) {
        int np = 0; float tsl = 0.f, tso = 0.f;
        #pragma unroll
        for (int i = 0; i < 8; i++) { np += s_wc[i]; tsl += s_sl[i]; tso += s_so[i]; }
        g_np_part[rid] = np;
        g_loc_part[rid] = (double)tsl; g_obj_part[rid] = (double)tso;
        s_base = np ? atomicAdd(&g_npt, np) : 0;        // one spread atomic per block
    }
    __syncthreads();
    if (pos) {
        int off = 0;
        for (int i = 0; i < w; i++) off += s_wc[i];
        g_pos[s_base + off + rank] = make_int2(b * NP + p, conf_t);
    }
}

// ---------------- fixup for forced priors (deltas only) ----------------
__global__ void __launch_bounds__(64) k_fix(
    const float* __restrict__ loc, const float2* __restrict__ obj,
    const float4* __restrict__ priors, const float* __restrict__ targets)
{
    const int b = blockIdx.x, t = threadIdx.x;
    __shared__ int wp[NO];
    __shared__ float  s_loc[64], s_obj[64];
    __shared__ int    s_np[64];
    if (t < NO) wp[t] = (int)(~(unsigned)g_best[b * NO + t]);
    __syncthreads();

    float locd = 0.f, objd = 0.f; int npd = 0;
    if (t < NO) {
        bool alive = true;                    // last o wins on duplicate winners
        for (int o2 = t + 1; o2 < NO; o2++) if (wp[o2] == wp[t]) { alive = false; break; }
        if (alive) {
            const int p = wp[t], o = t;
            const size_t g = (size_t)b * NP + p;
            float4 pr = priors[p];
            float px1 = pr.x - pr.z * 0.5f, py1 = pr.y - pr.w * 0.5f;
            float px2 = pr.x + pr.z * 0.5f, py2 = pr.y + pr.w * 0.5f;
            float areaP = (px2 - px1) * (py2 - py1);
            float bestv = -1.f; int besto = 0;
            for (int o2 = 0; o2 < NO; o2++) {
                const float* tp = targets + ((size_t)b * NO + o2) * 5;
                float4 bx = make_float4(tp[0], tp[1], tp[2], tp[3]);
                float area = (bx.z - bx.x) * (bx.w - bx.y);
                float ix = fmaxf(fminf(px2, bx.z) - fmaxf(px1, bx.x), 0.f);
                float iy = fmaxf(fminf(py2, bx.w) - fmaxf(py1, bx.y), 0.f);
                float inter = ix * iy;
                float iou = inter / (area + areaP - inter);
                if (iou > bestv) { bestv = iou; besto = o2; }
            }
            g_ce[g] = 0.f;                     // forced prior is positive -> not mined
            const float* tpn = targets + ((size_t)b * NO + o) * 5;
            float4 tbn = make_float4(tpn[0], tpn[1], tpn[2], tpn[3]);
            int ct_new = (int)tpn[4] + 1;
            float sl_new = sl1_row(loc + g * 4, pr, tbn);
            bool pos_old = bestv >= 0.5f;
            if (pos_old) {
                const float* tpo = targets + ((size_t)b * NO + besto) * 5;
                float4 tbo = make_float4(tpo[0], tpo[1], tpo[2], tpo[3]);
                int ct_old = (int)tpo[4] + 1;
                locd = sl_new - sl1_row(loc + g * 4, pr, tbo);
                g_fixbuf[b * 100 + 2 * t]     = make_int2((int)g,  ct_new);
                g_fixbuf[b * 100 + 2 * t + 1] = make_int2((int)g, -ct_old);
            } else {
                float2 ob = obj[g];
                float lseo = fmaxf(ob.x, ob.y) + log1pf(__expf(-fabsf(ob.x - ob.y)));
                objd = lseo - ob.y;
                locd = sl_new;
                npd = 1;
                g_fixbuf[b * 100 + 2 * t] = make_int2((int)g, ct_new);
            }
        }
    }
    s_loc[t] = locd; s_obj[t] = objd; s_np[t] = npd;
    __syncthreads();
    if (t == 0) {
        float tl = 0.f, to = 0.f; int tn = 0;
        for (int i = 0; i < 64; i++) { tl += s_loc[i]; to += s_obj[i]; tn += s_np[i]; }
        g_fixloc[b] = (double)tl; g_fixobj[b] = (double)to; g_fixnpos[b] = tn;
    }
}

// ---------------- positives-only conf CE (warp per 2 items, grid-stride) -------
__global__ void __launch_bounds__(256) k_posconf(const float* __restrict__ conf,
                                                 const float2* __restrict__ obj) {
    const int gwarp = (blockIdx.x * 256 + threadIdx.x) >> 5;
    const int lane = threadIdx.x & 31;
    const int n = g_npt;
    const int ntot = n + NB * 100;
    double dacc = 0.0;
    for (int i0 = gwarp * 2; i0 < ntot; i0 += 2 * NPCW) {
        int gi[2]; int ct[2]; float sg[2];
        #pragma unroll
        for (int u = 0; u < 2; u++) {
            int i = i0 + u;
            if (i >= ntot) { gi[u] = 0; ct[u] = 1; sg[u] = 0.f; }
            else if (i < n) { int2 e = g_pos[i]; gi[u] = e.x; ct[u] = e.y; sg[u] = 1.f; }
            else {
                int2 e = g_fixbuf[i - n];
                if (e.y == 0) { gi[u] = 0; ct[u] = 1; sg[u] = 0.f; }
                else { gi[u] = e.x; ct[u] = (e.y > 0) ? e.y : -e.y; sg[u] = (e.y > 0) ? 1.f : -1.f; }
            }
        }
        float v0[2], v1[2], v2[2], e2[2];
        #pragma unroll
        for (int u = 0; u < 2; u++) {
            const float* cr = conf + (size_t)gi[u] * NC;
            v0[u] = cr[lane];
            v1[u] = cr[lane + 32];
            v2[u] = (lane < NC - 64) ? cr[lane + 64] : 0.f;
        }
        #pragma unroll
        for (int u = 0; u < 2; u++)
            e2[u] = __expf(v0[u]) + __expf(v1[u]) + ((lane < NC - 64) ? __expf(v2[u]) : 0.f);
        #pragma unroll
        for (int s = 16; s; s >>= 1) {
            e2[0] += __shfl_xor_sync(FULLMASK, e2[0], s);
            e2[1] += __shfl_xor_sync(FULLMASK, e2[1], s);
        }
        #pragma unroll
        for (int u = 0; u < 2; u++) {
            int j = ct[u] - 1;
            float cand = (j < 32) ? v0[u] : ((j < 64) ? v1[u] : v2[u]);
            float ctv = __shfl_sync(FULLMASK, cand, j & 31);
            if (lane == 0 && sg[u] != 0.f) {
                float2 ob = obj[gi[u]];
                float lseo = fmaxf(ob.x, ob.y) + log1pf(__expf(-fabsf(ob.x - ob.y)));
                dacc += (double)sg[u] * (double)(__logf(e2[u]) + lseo - ob.y - ctv);
            }
        }
    }
    if (lane == 0) g_pcpart[gwarp] = dacc;
}

// ---------------- hard-negative mining: exact top-k sum per row ----------------
__global__ void __launch_bounds__(512) k_mine() {
    const int b = blockIdx.x;
    const float* arr = g_ce + (size_t)b * NP;

    __shared__ int s_k;
    __shared__ int s_cnt[16];
    __shared__ double s_sum[16];
    const int wid = threadIdx.x >> 5, lane = threadIdx.x & 31;

    if (threadIdx.x < 64) {
        int v = g_np_part[b * NPB + threadIdx.x];
        #pragma unroll
        for (int s = 16; s; s >>= 1) v += __shfl_xor_sync(FULLMASK, v, s);
        if (lane == 0) s_cnt[wid] = v;
    }
    __syncthreads();
    if (threadIdx.x == 0) {
        int k = 3 * (s_cnt[0] + s_cnt[1] + g_fixnpos[b]);
        s_k = (k > NP - 1) ? (NP - 1) : k;
    }

    float vals[32];
    #pragma unroll
    for (int j = 0; j < 32; j++) {
        int i = threadIdx.x + j * 512;
        vals[j] = (i < NP) ? arr[i] : 0.f;
    }
    __syncthreads();
    const int k = s_k;

    unsigned lo = 0u, hi = 0x7f7fffffu;   // values >= 0: bit order == value order
    while (lo < hi) {
        unsigned mid = lo + (hi - lo + 1) / 2;
        int c = 0;
        #pragma unroll
        for (int j = 0; j < 32; j++) c += (__float_as_uint(vals[j]) >= mid);
        #pragma unroll
        for (int s = 16; s; s >>= 1) c += __shfl_xor_sync(FULLMASK, c, s);
        if (lane == 0) s_cnt[wid] = c;
        __syncthreads();
        int tot = 0;
        #pragma unroll
        for (int w2 = 0; w2 < 16; w2++) tot += s_cnt[w2];
        if (tot >= k) lo = mid; else hi = mid - 1;
        __syncthreads();
    }
    float vf = __uint_as_float(lo);

    int cgt = 0; double sgt = 0.0;
    #pragma unroll
    for (int j = 0; j < 32; j++)
        if (__float_as_uint(vals[j]) > lo) { cgt++; sgt += (double)vals[j]; }
    #pragma unroll
    for (int s = 16; s; s >>= 1) {
        cgt += __shfl_xor_sync(FULLMASK, cgt, s);
        sgt += __shfl_xor_sync(FULLMASK, sgt, s);
    }
    if (lane == 0) { s_cnt[wid] = cgt; s_sum[wid] = sgt; }
    __syncthreads();
    if (threadIdx.x == 0) {
        int tc = 0; double ts = 0.0;
        #pragma unroll
        for (int w2 = 0; w2 < 16; w2++) { tc += s_cnt[w2]; ts += s_sum[w2]; }
        g_minepart[b] = ts + (double)(k - tc) * (double)vf;
    }
}

// ---------------- finalize ----------------
__global__ void __launch_bounds__(256) k_final(float* out) {
    const int t = threadIdx.x;
    __shared__ double red[256 * 4];
    __shared__ int    redn[256];
    double a_loc = 0.0, a_obj = 0.0, a_pc = 0.0, a_mx = 0.0;
    int a_n = 0;
    for (int i = t; i < NRID; i += 256) {
        a_loc += g_loc_part[i]; a_obj += g_obj_part[i]; a_n += g_np_part[i];
    }
    for (int i = t; i < NPCW; i += 256) a_pc += g_pcpart[i];
    for (int i = t; i < NB; i += 256) {
        a_loc += g_fixloc[i]; a_obj += g_fixobj[i]; a_n += g_fixnpos[i];
        a_mx += g_minepart[i];
    }
    red[t] = a_loc; red[256 + t] = a_obj; red[512 + t] = a_pc; red[768 + t] = a_mx;
    redn[t] = a_n;
    __syncthreads();
    for (int s = 128; s; s >>= 1) {
        if (t < s) {
            red[t] += red[t + s]; red[256 + t] += red[256 + t + s];
            red[512 + t] += red[512 + t + s]; red[768 + t] += red[768 + t + s];
            redn[t] += redn[t + s];
        }
        __syncthreads();
    }
    if (t == 0) {
        double N = (double)redn[0];
        double S = red[768];
        out[0] = (float)(red[0] / N);
        out[1] = (float)((red[512] + S) / N);
        out[2] = (float)((red[256] + S) / N);
    }
}

extern "C" void kernel_launch(void* const* d_in, const int* in_sizes, int n_in,
                              void* d_out, int out_size) {
    const float*  loc     = (const float*)d_in[0];
    const float*  conf    = (const float*)d_in[1];
    const float2* obj     = (const float2*)d_in[2];
    const float4* priors  = (const float4*)d_in[3];
    const float*  targets = (const float*)d_in[4];
    float* out = (float*)d_out;

    k_init<<<26, 256>>>();
    k_bestprior<<<dim3(NO / OGRP, NB), 256>>>(priors, targets);
    k_matchpos<<<dim3(NPB, NB), 256>>>(loc, obj, priors, targets);
    k_fix<<<NB, 64>>>(loc, obj, priors, targets);
    k_posconf<<<NPCW / 8, 256>>>(conf, obj);
    k_mine<<<NB, 512>>>();
    k_final<<<1, 256>>>(out);
}

// round 13
// speedup vs baseline: 3.2622x; 3.2622x over previous
#include <cuda_runtime.h>
#include <cuda_bf16.h>
#include <math.h>

#define NB 64
#define NP 16320
#define NC 81
#define NO 50
#define NPB 64              // prior-blocks per batch (64*256 = 16384 >= NP)
#define NRID (NB*NPB)       // 4096 regions
#define NPCW 2048           // posconf warps
#define FULLMASK 0xffffffffu

// ---------------- static scratch (no allocations) ----------------
__device__ unsigned long long g_best[NB * NO];
__device__ float    g_ce[(size_t)NB * NP];    // mining array (pos -> 0)
__device__ int2     g_pos[(size_t)NB * NP];   // compact positive list {g, conf_t}
__device__ int      g_npt;
__device__ int      g_np_part[NRID];
__device__ double   g_loc_part[NRID];
__device__ double   g_obj_part[NRID];
__device__ int      g_fixnpos[NB];
__device__ double   g_fixloc[NB];
__device__ double   g_fixobj[NB];
__device__ int2     g_fixbuf[NB * 100];       // (g, signed conf_t), ct==0 invalid
__device__ double   g_pcpart[NPCW];
__device__ double   g_minepart[NB];

__device__ __forceinline__ float sl1_row(const float* lp, float4 pr, float4 tb) {
    float gx = ((tb.x + tb.z) * 0.5f - pr.x) / (0.1f * pr.z);
    float gy = ((tb.y + tb.w) * 0.5f - pr.y) / (0.1f * pr.w);
    float gw = logf((tb.z - tb.x) / pr.z) / 0.2f;
    float gh = logf((tb.w - tb.y) / pr.w) / 0.2f;
    float d0 = lp[0] - gx, d1 = lp[1] - gy, d2 = lp[2] - gw, d3 = lp[3] - gh;
    #define SL1(d) ((fabsf(d) < 1.f) ? 0.5f * (d) * (d) : fabsf(d) - 0.5f)
    return SL1(d0) + SL1(d1) + SL1(d2) + SL1(d3);
    #undef SL1
}

// ---------------- init ----------------
__global__ void k_init() {
    int i = blockIdx.x * blockDim.x + threadIdx.x;
    if (i == 0) g_npt = 0;
    if (i < NRID) { g_np_part[i] = 0; g_loc_part[i] = 0.0; g_obj_part[i] = 0.0; }
    if (i < NB) { g_minepart[i] = 0.0; g_fixnpos[i] = 0; g_fixloc[i] = 0.0; g_fixobj[i] = 0.0; }
    if (i < NB * 100) g_fixbuf[i] = make_int2(0, 0);
    if (i < NB * NO) g_best[i] = 0x00000000FFFFFFFFull;   // iou=0, p=0
}

// ---------------- fused match + per-prior losses ----------------
__global__ void __launch_bounds__(256) k_matchpos(
    const float* __restrict__ loc, const float2* __restrict__ obj,
    const float4* __restrict__ priors, const float* __restrict__ targets)
{
    const int b = blockIdx.y, pb = blockIdx.x, rid = b * NPB + pb;
    const int t = threadIdx.x, lane = t & 31, w = t >> 5;
    __shared__ float4 tbox[NO];
    __shared__ float  tarea[NO], tlabel[NO];
    __shared__ unsigned long long s_cand[NO][8];
    __shared__ int   s_wc[8];
    __shared__ float s_sl[8], s_so[8];
    __shared__ int   s_base;

    if (t < NO) {
        const float* tp = targets + ((size_t)b * NO + t) * 5;
        float4 bx = make_float4(tp[0], tp[1], tp[2], tp[3]);
        tbox[t] = bx;
        tarea[t] = (bx.z - bx.x) * (bx.w - bx.y);
        tlabel[t] = tp[4];
    }
    __syncthreads();

    const int p = pb * 256 + t;
    const bool valid = p < NP;
    float4 pr;
    float px1, py1, px2, py2, areaP;
    if (valid) {
        pr = priors[p];
        px1 = pr.x - pr.z * 0.5f; py1 = pr.y - pr.w * 0.5f;
        px2 = pr.x + pr.z * 0.5f; py2 = pr.y + pr.w * 0.5f;
        areaP = (px2 - px1) * (py2 - py1);
    } else {
        px1 = py1 = px2 = py2 = 1e30f;  // inter = 0 -> iou = 0
        areaP = 0.f;
    }
    const int wbase = pb * 256 + (t & ~31);

    float bestv = -1.f; int besto = 0;
    #pragma unroll 2
    for (int o = 0; o < NO; o++) {
        float4 tbo = tbox[o];
        float ix = fmaxf(fminf(px2, tbo.z) - fmaxf(px1, tbo.x), 0.f);
        float iy = fmaxf(fminf(py2, tbo.w) - fmaxf(py1, tbo.y), 0.f);
        float inter = ix * iy;
        float iou = inter / (tarea[o] + areaP - inter);
        if (iou > bestv) { bestv = iou; besto = o; }    // first max (tie rule)
        unsigned bits = __float_as_uint(iou);           // iou >= 0: order-preserving
        unsigned mx = __reduce_max_sync(FULLMASK, bits);
        unsigned ball = __ballot_sync(FULLMASK, bits == mx);
        if (lane == 0) {
            int wl = __ffs(ball) - 1;                   // lowest lane = lowest p
            s_cand[o][w] = (((unsigned long long)mx) << 32) |
                           (unsigned)(~(unsigned)(wbase + wl));
        }
    }

    // per-prior losses (unforced state; forcing deltas applied in k_fix)
    bool pos = false; int conf_t = 0; float lossl = 0.f, ceo = 0.f;
    if (valid) {
        conf_t = (bestv < 0.5f) ? 0 : ((int)tlabel[besto] + 1);
        pos = conf_t > 0;
        size_t g = (size_t)b * NP + p;
        float2 ob = obj[g];
        float lseo = fmaxf(ob.x, ob.y) + log1pf(__expf(-fabsf(ob.x - ob.y)));
        g_ce[g] = pos ? 0.f : (lseo - ob.x);            // ce_c(neg) == ce_o(neg)
        if (pos) {
            ceo = lseo - ob.y;
            lossl = sl1_row(loc + g * 4, pr, tbox[besto]);
        }
    }

    unsigned bal = __ballot_sync(FULLMASK, pos);
    int rank = __popc(bal & ((1u << lane) - 1));
    float sl = lossl, so = ceo;
    #pragma unroll
    for (int s = 16; s; s >>= 1) {
        sl += __shfl_xor_sync(FULLMASK, sl, s);
        so += __shfl_xor_sync(FULLMASK, so, s);
    }
    if (lane == 0) { s_wc[w] = __popc(bal); s_sl[w] = sl; s_so[w] = so; }
    __syncthreads();

    // block-level per-o argmax reduce + spread-address global atomicMax
    if (t < NO) {
        unsigned long long bst = s_cand[t][0];
        #pragma unroll
        for (int i = 1; i < 8; i++) { unsigned long long c = s_cand[t][i]; if (c > bst) bst = c; }
        atomicMax(&g_best[b * NO + t], bst);
    }

    if (t == 0) {
        int np = 0; float tsl = 0.f, tso = 0.f;
        #pragma unroll
        for (int i = 0; i < 8; i++) { np += s_wc[i]; tsl += s_sl[i]; tso += s_so[i]; }
        g_np_part[rid] = np;
        g_loc_part[rid] = (double)tsl; g_obj_part[rid] = (double)tso;
        s_base = np ? atomicAdd(&g_npt, np) : 0;        // ONE atomic per block
    }
    __syncthreads();
    if (pos) {
        int off = 0;
        for (int i = 0; i < w; i++) off += s_wc[i];
        g_pos[s_base + off + rank] = make_int2(b * NP + p, conf_t);
    }
}

// ---------------- fixup for forced priors: warp per (b,o), parallel truths ----
__global__ void __launch_bounds__(256) k_fix(
    const float* __restrict__ loc, const float2* __restrict__ obj,
    const float4* __restrict__ priors, const float* __restrict__ targets)
{
    const int b = blockIdx.x;
    const int t = threadIdx.x, lane = t & 31, w = t >> 5;   // 8 warps
    __shared__ int    wp[NO];
    __shared__ float4 tbox[NO];
    __shared__ float  tarea[NO], tlabel[NO];
    __shared__ float  s_loc[8], s_obj[8];
    __shared__ int    s_np[8];

    if (t < NO) {
        wp[t] = (int)(~(unsigned)g_best[b * NO + t]);
        const float* tp = targets + ((size_t)b * NO + t) * 5;
        float4 bx = make_float4(tp[0], tp[1], tp[2], tp[3]);
        tbox[t] = bx;
        tarea[t] = (bx.z - bx.x) * (bx.w - bx.y);
        tlabel[t] = tp[4];
    }
    __syncthreads();

    float locd = 0.f, objd = 0.f; int npd = 0;
    for (int o = w; o < NO; o += 8) {
        const int p = wp[o];
        bool alive = true;                        // last o wins on duplicate winners
        for (int o2 = o + 1; o2 < NO; o2++) if (wp[o2] == p) { alive = false; break; }
        if (!alive) continue;                     // uniform per warp

        const size_t g = (size_t)b * NP + p;
        float4 pr = priors[p];
        float px1 = pr.x - pr.z * 0.5f, py1 = pr.y - pr.w * 0.5f;
        float px2 = pr.x + pr.z * 0.5f, py2 = pr.y + pr.w * 0.5f;
        float areaP = (px2 - px1) * (py2 - py1);

        // unforced best over truths: lane handles truths {lane, lane+32}
        float bv = -1.f; int bo = 0;
        #pragma unroll
        for (int u = 0; u < 2; u++) {
            int j = lane + u * 32;
            if (j < NO) {
                float4 tbo = tbox[j];
                float ix = fmaxf(fminf(px2, tbo.z) - fmaxf(px1, tbo.x), 0.f);
                float iy = fmaxf(fminf(py2, tbo.w) - fmaxf(py1, tbo.y), 0.f);
                float inter = ix * iy;
                float iou = inter / (tarea[j] + areaP - inter);
                if (iou > bv) { bv = iou; bo = j; }  // strict: lower j wins ties
            }
        }
        unsigned long long pk = (((unsigned long long)__float_as_uint(fmaxf(bv, 0.f))) << 32)
                              | (unsigned)(64 - bo);   // higher iou; tie -> lower o
        #pragma unroll
        for (int s = 16; s; s >>= 1) {
            unsigned long long o2v = __shfl_xor_sync(FULLMASK, pk, s);
            if (o2v > pk) pk = o2v;
        }
        float bestv = __uint_as_float((unsigned)(pk >> 32));
        int   besto = 64 - (int)(pk & 0xffffffffu);

        if (lane == 0) {
            g_ce[g] = 0.f;                         // forced prior is positive -> not mined
            float4 tbn = tbox[o];
            int ct_new = (int)tlabel[o] + 1;
            float sl_new = sl1_row(loc + g * 4, pr, tbn);
            if (bestv >= 0.5f) {                   // was already positive: swap truth
                float4 tbo2 = tbox[besto];
                int ct_old = (int)tlabel[besto] + 1;
                locd += sl_new - sl1_row(loc + g * 4, pr, tbo2);
                g_fixbuf[b * 100 + 2 * o]     = make_int2((int)g,  ct_new);
                g_fixbuf[b * 100 + 2 * o + 1] = make_int2((int)g, -ct_old);
            } else {                               // was negative: becomes positive
                float2 ob = obj[g];
                float lseo = fmaxf(ob.x, ob.y) + log1pf(__expf(-fabsf(ob.x - ob.y)));
                objd += lseo - ob.y;
                locd += sl_new;
                npd  += 1;
                g_fixbuf[b * 100 + 2 * o] = make_int2((int)g, ct_new);
            }
        }
    }
    if (lane == 0) { s_loc[w] = locd; s_obj[w] = objd; s_np[w] = npd; }
    __syncthreads();
    if (t == 0) {
        float tl = 0.f, to = 0.f; int tn = 0;
        #pragma unroll
        for (int i = 0; i < 8; i++) { tl += s_loc[i]; to += s_obj[i]; tn += s_np[i]; }
        g_fixloc[b] = (double)tl; g_fixobj[b] = (double)to; g_fixnpos[b] = tn;
    }
}

// ---------------- positives-only conf CE (warp per 2 items, grid-stride) -------
__global__ void __launch_bounds__(256) k_posconf(const float* __restrict__ conf,
                                                 const float2* __restrict__ obj) {
    const int gwarp = (blockIdx.x * 256 + threadIdx.x) >> 5;
    const int lane = threadIdx.x & 31;
    const int n = g_npt;
    const int ntot = n + NB * 100;
    double dacc = 0.0;
    for (int i0 = gwarp * 2; i0 < ntot; i0 += 2 * NPCW) {
        int gi[2]; int ct[2]; float sg[2];
        #pragma unroll
        for (int u = 0; u < 2; u++) {
            int i = i0 + u;
            if (i >= ntot) { gi[u] = 0; ct[u] = 1; sg[u] = 0.f; }
            else if (i < n) { int2 e = g_pos[i]; gi[u] = e.x; ct[u] = e.y; sg[u] = 1.f; }
            else {
                int2 e = g_fixbuf[i - n];
                if (e.y == 0) { gi[u] = 0; ct[u] = 1; sg[u] = 0.f; }
                else { gi[u] = e.x; ct[u] = (e.y > 0) ? e.y : -e.y; sg[u] = (e.y > 0) ? 1.f : -1.f; }
            }
        }
        float v0[2], v1[2], v2[2], e2[2];
        #pragma unroll
        for (int u = 0; u < 2; u++) {
            const float* cr = conf + (size_t)gi[u] * NC;
            v0[u] = cr[lane];
            v1[u] = cr[lane + 32];
            v2[u] = (lane < NC - 64) ? cr[lane + 64] : 0.f;
        }
        #pragma unroll
        for (int u = 0; u < 2; u++)
            e2[u] = __expf(v0[u]) + __expf(v1[u]) + ((lane < NC - 64) ? __expf(v2[u]) : 0.f);
        #pragma unroll
        for (int s = 16; s; s >>= 1) {
            e2[0] += __shfl_xor_sync(FULLMASK, e2[0], s);
            e2[1] += __shfl_xor_sync(FULLMASK, e2[1], s);
        }
        #pragma unroll
        for (int u = 0; u < 2; u++) {
            int j = ct[u] - 1;
            float cand = (j < 32) ? v0[u] : ((j < 64) ? v1[u] : v2[u]);
            float ctv = __shfl_sync(FULLMASK, cand, j & 31);
            if (lane == 0 && sg[u] != 0.f) {
                float2 ob = obj[gi[u]];
                float lseo = fmaxf(ob.x, ob.y) + log1pf(__expf(-fabsf(ob.x - ob.y)));
                dacc += (double)sg[u] * (double)(__logf(e2[u]) + lseo - ob.y - ctv);
            }
        }
    }
    if (lane == 0) g_pcpart[gwarp] = dacc;
}

// ---------------- hard-negative mining: exact top-k sum per row ----------------
__global__ void __launch_bounds__(512) k_mine() {
    const int b = blockIdx.x;
    const float* arr = g_ce + (size_t)b * NP;

    __shared__ int s_k;
    __shared__ int s_cnt[16];
    __shared__ double s_sum[16];
    const int wid = threadIdx.x >> 5, lane = threadIdx.x & 31;

    if (threadIdx.x < 64) {
        int v = g_np_part[b * NPB + threadIdx.x];
        #pragma unroll
        for (int s = 16; s; s >>= 1) v += __shfl_xor_sync(FULLMASK, v, s);
        if (lane == 0) s_cnt[wid] = v;
    }
    __syncthreads();
    if (threadIdx.x == 0) {
        int k = 3 * (s_cnt[0] + s_cnt[1] + g_fixnpos[b]);
        s_k = (k > NP - 1) ? (NP - 1) : k;
    }

    float vals[32];
    #pragma unroll
    for (int j = 0; j < 32; j++) {
        int i = threadIdx.x + j * 512;
        vals[j] = (i < NP) ? arr[i] : 0.f;
    }
    __syncthreads();
    const int k = s_k;

    unsigned lo = 0u, hi = 0x7f7fffffu;   // values >= 0: bit order == value order
    while (lo < hi) {
        unsigned mid = lo + (hi - lo + 1) / 2;
        int c = 0;
        #pragma unroll
        for (int j = 0; j < 32; j++) c += (__float_as_uint(vals[j]) >= mid);
        #pragma unroll
        for (int s = 16; s; s >>= 1) c += __shfl_xor_sync(FULLMASK, c, s);
        if (lane == 0) s_cnt[wid] = c;
        __syncthreads();
        int tot = 0;
        #pragma unroll
        for (int w2 = 0; w2 < 16; w2++) tot += s_cnt[w2];
        if (tot >= k) lo = mid; else hi = mid - 1;
        __syncthreads();
    }
    float vf = __uint_as_float(lo);

    int cgt = 0; double sgt = 0.0;
    #pragma unroll
    for (int j = 0; j < 32; j++)
        if (__float_as_uint(vals[j]) > lo) { cgt++; sgt += (double)vals[j]; }
    #pragma unroll
    for (int s = 16; s; s >>= 1) {
        cgt += __shfl_xor_sync(FULLMASK, cgt, s);
        sgt += __shfl_xor_sync(FULLMASK, sgt, s);
    }
    if (lane == 0) { s_cnt[wid] = cgt; s_sum[wid] = sgt; }
    __syncthreads();
    if (threadIdx.x == 0) {
        int tc = 0; double ts = 0.0;
        #pragma unroll
        for (int w2 = 0; w2 < 16; w2++) { tc += s_cnt[w2]; ts += s_sum[w2]; }
        g_minepart[b] = ts + (double)(k - tc) * (double)vf;
    }
}

// ---------------- finalize ----------------
__global__ void __launch_bounds__(256) k_final(float* out) {
    const int t = threadIdx.x;
    __shared__ double red[256 * 4];
    __shared__ int    redn[256];
    double a_loc = 0.0, a_obj = 0.0, a_pc = 0.0, a_mx = 0.0;
    int a_n = 0;
    for (int i = t; i < NRID; i += 256) {
        a_loc += g_loc_part[i]; a_obj += g_obj_part[i]; a_n += g_np_part[i];
    }
    for (int i = t; i < NPCW; i += 256) a_pc += g_pcpart[i];
    for (int i = t; i < NB; i += 256) {
        a_loc += g_fixloc[i]; a_obj += g_fixobj[i]; a_n += g_fixnpos[i];
        a_mx += g_minepart[i];
    }
    red[t] = a_loc; red[256 + t] = a_obj; red[512 + t] = a_pc; red[768 + t] = a_mx;
    redn[t] = a_n;
    __syncthreads();
    for (int s = 128; s; s >>= 1) {
        if (t < s) {
            red[t] += red[t + s]; red[256 + t] += red[256 + t + s];
            red[512 + t] += red[512 + t + s]; red[768 + t] += red[768 + t + s];
            redn[t] += redn[t + s];
        }
        __syncthreads();
    }
    if (t == 0) {
        double N = (double)redn[0];
        double S = red[768];
        out[0] = (float)(red[0] / N);
        out[1] = (float)((red[512] + S) / N);
        out[2] = (float)((red[256] + S) / N);
    }
}

extern "C" void kernel_launch(void* const* d_in, const int* in_sizes, int n_in,
                              void* d_out, int out_size) {
    const float*  loc     = (const float*)d_in[0];
    const float*  conf    = (const float*)d_in[1];
    const float2* obj     = (const float2*)d_in[2];
    const float4* priors  = (const float4*)d_in[3];
    const float*  targets = (const float*)d_in[4];
    float* out = (float*)d_out;

    k_init<<<26, 256>>>();
    k_matchpos<<<dim3(NPB, NB), 256>>>(loc, obj, priors, targets);
    k_fix<<<NB, 256>>>(loc, obj, priors, targets);
    k_posconf<<<NPCW / 8, 256>>>(conf, obj);
    k_mine<<<NB, 512>>>();
    k_final<<<1, 256>>>(out);
}